// round 1
// baseline (speedup 1.0000x reference)
#include <cuda_runtime.h>
#include <math.h>

#define OMEGA 1.5f
#define NROW  384
#define MID   256
#define NR    100     // rank R

#define BM 128        // j tile
#define BN 128        // k tile
#define CH 25         // r chunk (100 = 4*25)

// Factor matrices, stored transposed: g_X[r*NROW + row]
__device__ float g_A[NR * NROW];
__device__ float g_B[NR * NROW];
__device__ float g_C[NR * NROW];

// ---------------------------------------------------------------------------
// Packed f32x2 helpers (FFMA2 / pack)
// ---------------------------------------------------------------------------
__device__ __forceinline__ unsigned long long ffma2(unsigned long long a,
                                                    unsigned long long b,
                                                    unsigned long long c) {
    unsigned long long d;
    asm("fma.rn.f32x2 %0, %1, %2, %3;" : "=l"(d) : "l"(a), "l"(b), "l"(c));
    return d;
}
__device__ __forceinline__ unsigned long long pack2(float x) {
    unsigned long long d;
    asm("mov.b64 %0, {%1, %1};" : "=l"(d) : "f"(x));
    return d;
}

// ---------------------------------------------------------------------------
// Factor networks: one block per row, 256 threads.
// net: 0 -> g_A, 1 -> g_B, 2 -> g_C.  depth: 2 or 3 sine layers total.
// W1/b1: [MID,1]/[MID]; W2/b2: [MID,MID] or [NR,MID]; W3/b3: [NR,MID]/[NR]
// ---------------------------------------------------------------------------
__global__ void factor_kernel(const float* __restrict__ in,
                              const float* __restrict__ W1, const float* __restrict__ b1,
                              const float* __restrict__ W2, const float* __restrict__ b2,
                              const float* __restrict__ W3, const float* __restrict__ b3,
                              int net, int depth)
{
    const int i = blockIdx.x;
    const int t = threadIdx.x;
    __shared__ float h[MID];

    const float x = in[i];
    h[t] = sinf(OMEGA * (x * W1[t] + b1[t]));
    __syncthreads();

    if (depth == 3) {
        // middle sine layer (C net): h <- sin(omega * (h @ W2^T + b2))
        float s = b2[t];
        const float* w = W2 + t * MID;
        #pragma unroll 8
        for (int m = 0; m < MID; m++) s += h[m] * w[m];
        __syncthreads();            // everyone done reading h
        h[t] = sinf(OMEGA * s);
        __syncthreads();
    }

    if (t < NR) {
        const float* wf = (depth == 3 ? W3 : W2) + t * MID;
        float s = (depth == 3 ? b3 : b2)[t];
        #pragma unroll 8
        for (int m = 0; m < MID; m++) s += h[m] * wf[m];
        float* out = (net == 0) ? g_A : (net == 1) ? g_B : g_C;
        out[t * NROW + i] = s;      // transposed: [r][row]
    }
}

// ---------------------------------------------------------------------------
// Contraction: out[i,j,k] = sum_r A[i,r]*B[j,r]*C[k,r]
// Grid: (k_tiles=3, j_tiles=3, i=384). Block 256 threads = 16(tx:k) x 16(ty:j).
// Each thread: 8x8 micro-tile, accumulated as 32 packed f32x2 regs.
// A[i,r] is folded into the shared B tile at fill time.
// ---------------------------------------------------------------------------
__global__ void __launch_bounds__(256, 2) contract_kernel(float* __restrict__ out)
{
    const int i  = blockIdx.z;
    const int jb = blockIdx.y * BM;
    const int kb = blockIdx.x * BN;
    const int tid = threadIdx.x;
    const int tx = tid & 15;   // k octet index
    const int ty = tid >> 4;   // j octet index

    __shared__ float sB[CH][BM];   // A[i,r] * B[j,r]
    __shared__ float sC[CH][BN];   // C[k,r]

    unsigned long long acc[8][4];
    #pragma unroll
    for (int a = 0; a < 8; a++)
        #pragma unroll
        for (int b = 0; b < 4; b++) acc[a][b] = 0ull;

    for (int c0 = 0; c0 < NR; c0 += CH) {
        // fill shared (coalesced along row dim)
        for (int idx = tid; idx < CH * BM; idx += 256) {
            const int rr  = idx >> 7;      // BM == BN == 128
            const int col = idx & 127;
            const int r   = c0 + rr;
            const float a = g_A[r * NROW + i];
            sB[rr][col] = a * g_B[r * NROW + jb + col];
            sC[rr][col] =     g_C[r * NROW + kb + col];
        }
        __syncthreads();

        #pragma unroll 5
        for (int r = 0; r < CH; r++) {
            const float4* bp = reinterpret_cast<const float4*>(&sB[r][ty * 8]);
            const ulonglong2* cp = reinterpret_cast<const ulonglong2*>(&sC[r][tx * 8]);
            const float4 b0 = bp[0];
            const float4 b1 = bp[1];
            const ulonglong2 cv0 = cp[0];
            const ulonglong2 cv1 = cp[1];
            float bs[8] = {b0.x, b0.y, b0.z, b0.w, b1.x, b1.y, b1.z, b1.w};
            #pragma unroll
            for (int jj = 0; jj < 8; jj++) {
                const unsigned long long bb = pack2(bs[jj]);
                acc[jj][0] = ffma2(bb, cv0.x, acc[jj][0]);
                acc[jj][1] = ffma2(bb, cv0.y, acc[jj][1]);
                acc[jj][2] = ffma2(bb, cv1.x, acc[jj][2]);
                acc[jj][3] = ffma2(bb, cv1.y, acc[jj][3]);
            }
        }
        __syncthreads();
    }

    // store: each thread writes 8 rows x 8 cols as 2x float4 per row
    const size_t base = ((size_t)i * NROW + (size_t)(jb + ty * 8)) * NROW
                        + (size_t)(kb + tx * 8);
    #pragma unroll
    for (int jj = 0; jj < 8; jj++) {
        float2 p0 = *reinterpret_cast<float2*>(&acc[jj][0]);
        float2 p1 = *reinterpret_cast<float2*>(&acc[jj][1]);
        float2 p2 = *reinterpret_cast<float2*>(&acc[jj][2]);
        float2 p3 = *reinterpret_cast<float2*>(&acc[jj][3]);
        float4* o = reinterpret_cast<float4*>(out + base + (size_t)jj * NROW);
        o[0] = make_float4(p0.x, p0.y, p1.x, p1.y);
        o[1] = make_float4(p2.x, p2.y, p3.x, p3.y);
    }
}

// ---------------------------------------------------------------------------
// kernel_launch
// Inputs (metadata order):
//  0 A_input 1 B_input 2 C_input
//  3 A_W1 4 A_b1 5 A_W2 6 A_b2
//  7 B_W1 8 B_b1 9 B_W2 10 B_b2
//  11 C_W1 12 C_b1 13 C_W2 14 C_b2 15 C_W3 16 C_b3
// ---------------------------------------------------------------------------
extern "C" void kernel_launch(void* const* d_in, const int* in_sizes, int n_in,
                              void* d_out, int out_size)
{
    const float* A_in = (const float*)d_in[0];
    const float* B_in = (const float*)d_in[1];
    const float* C_in = (const float*)d_in[2];
    const float* A_W1 = (const float*)d_in[3];
    const float* A_b1 = (const float*)d_in[4];
    const float* A_W2 = (const float*)d_in[5];
    const float* A_b2 = (const float*)d_in[6];
    const float* B_W1 = (const float*)d_in[7];
    const float* B_b1 = (const float*)d_in[8];
    const float* B_W2 = (const float*)d_in[9];
    const float* B_b2 = (const float*)d_in[10];
    const float* C_W1 = (const float*)d_in[11];
    const float* C_b1 = (const float*)d_in[12];
    const float* C_W2 = (const float*)d_in[13];
    const float* C_b2 = (const float*)d_in[14];
    const float* C_W3 = (const float*)d_in[15];
    const float* C_b3 = (const float*)d_in[16];

    float* out = (float*)d_out;

    factor_kernel<<<NROW, MID>>>(A_in, A_W1, A_b1, A_W2, A_b2, nullptr, nullptr, 0, 2);
    factor_kernel<<<NROW, MID>>>(B_in, B_W1, B_b1, B_W2, B_b2, nullptr, nullptr, 1, 2);
    factor_kernel<<<NROW, MID>>>(C_in, C_W1, C_b1, C_W2, C_b2, C_W3, C_b3, 2, 3);

    dim3 grid(NROW / BN, NROW / BM, NROW);   // (3, 3, 384)
    contract_kernel<<<grid, 256>>>(out);
}

// round 2
// speedup vs baseline: 1.2736x; 1.2736x over previous
#include <cuda_runtime.h>
#include <math.h>

#define OMEGA 1.5f
#define NROW  384
#define MID   256
#define NR    100     // rank R

#define BM 128        // j tile
#define BN 128        // k tile
#define CH 25         // r chunk (100 = 4*25)

// Factor matrices, stored transposed: g_X[r*NROW + row]
__device__ float g_A[NR * NROW];
__device__ float g_B[NR * NROW];
__device__ float g_C[NR * NROW];

// Transposed weights for coalesced factor-net reads
__device__ float g_AW2T[MID * NR];    // [m][n]
__device__ float g_BW2T[MID * NR];
__device__ float g_CW2T[MID * MID];
__device__ float g_CW3T[MID * NR];

// ---------------------------------------------------------------------------
// Packed f32x2 helpers
// ---------------------------------------------------------------------------
__device__ __forceinline__ unsigned long long ffma2(unsigned long long a,
                                                    unsigned long long b,
                                                    unsigned long long c) {
    unsigned long long d;
    asm("fma.rn.f32x2 %0, %1, %2, %3;" : "=l"(d) : "l"(a), "l"(b), "l"(c));
    return d;
}
__device__ __forceinline__ unsigned long long pack2(float x) {
    unsigned long long d;
    asm("mov.b64 %0, {%1, %1};" : "=l"(d) : "f"(x));
    return d;
}

// ---------------------------------------------------------------------------
// Transpose all second/third-layer weights (coalesced reads, tiny).
// AW2/BW2/CW3: [NR, MID] -> [MID, NR].  CW2: [MID, MID] -> [MID, MID].
// ---------------------------------------------------------------------------
__global__ void transpose_weights(const float* __restrict__ AW2,
                                  const float* __restrict__ BW2,
                                  const float* __restrict__ CW2,
                                  const float* __restrict__ CW3)
{
    const int idx = blockIdx.x * blockDim.x + threadIdx.x;
    if (idx < MID * MID) {
        const int n = idx / MID, m = idx % MID;
        g_CW2T[m * MID + n] = CW2[idx];
    }
    if (idx < NR * MID) {
        const int n = idx / MID, m = idx % MID;
        g_AW2T[m * NR + n] = AW2[idx];
        g_BW2T[m * NR + n] = BW2[idx];
        g_CW3T[m * NR + n] = CW3[idx];
    }
}

// ---------------------------------------------------------------------------
// Factor networks: one block per row, 256 threads, coalesced weight reads.
// net: 0 -> g_A, 1 -> g_B, 2 -> g_C.  depth: 2 or 3 sine layers total.
// ---------------------------------------------------------------------------
__global__ void factor_kernel(const float* __restrict__ in,
                              const float* __restrict__ W1, const float* __restrict__ b1,
                              const float* __restrict__ b2, const float* __restrict__ b3,
                              int net, int depth)
{
    const int i = blockIdx.x;
    const int t = threadIdx.x;
    __shared__ float h[MID];

    const float x = in[i];
    h[t] = sinf(OMEGA * (x * W1[t] + b1[t]));
    __syncthreads();

    if (depth == 3) {
        // middle sine layer (C net): h <- sin(omega * (h @ W2^T + b2))
        float s = b2[t];
        #pragma unroll 8
        for (int m = 0; m < MID; m++) s += h[m] * g_CW2T[m * MID + t];
        __syncthreads();
        h[t] = sinf(OMEGA * s);
        __syncthreads();
    }

    if (t < NR) {
        const float* wT = (net == 0) ? g_AW2T : (net == 1) ? g_BW2T : g_CW3T;
        float s = (depth == 3 ? b3 : b2)[t];
        #pragma unroll 8
        for (int m = 0; m < MID; m++) s += h[m] * wT[m * NR + t];
        float* out = (net == 0) ? g_A : (net == 1) ? g_B : g_C;
        out[t * NROW + i] = s;      // transposed: [r][row]
    }
}

// ---------------------------------------------------------------------------
// Contraction: out[i,j,k] = sum_r A[i,r]*B[j,r]*C[k,r]
// Grid: (3, 3, 384). Block 256 = 16(tx:k) x 16(ty:j). 8x8 micro-tile / thread.
// B is stored PRE-PACKED (duplicated f32x2) in shared; A[i,r] folded in.
// ---------------------------------------------------------------------------
__global__ void __launch_bounds__(256, 2) contract_kernel(float* __restrict__ out)
{
    const int i  = blockIdx.z;
    const int jb = blockIdx.y * BM;
    const int kb = blockIdx.x * BN;
    const int tid = threadIdx.x;
    const int tx = tid & 15;   // k octet index
    const int ty = tid >> 4;   // j octet index

    __shared__ alignas(16) unsigned long long sBp[CH][BM];  // packed A[i,r]*B[j,r]
    __shared__ alignas(16) float sC[CH][BN];                // C[k,r]

    unsigned long long acc[8][4];
    #pragma unroll
    for (int a = 0; a < 8; a++)
        #pragma unroll
        for (int b = 0; b < 4; b++) acc[a][b] = 0ull;

    for (int c0 = 0; c0 < NR; c0 += CH) {
        // fill shared (coalesced along row dim)
        for (int idx = tid; idx < CH * BM; idx += 256) {
            const int rr  = idx >> 7;      // BM == BN == 128
            const int col = idx & 127;
            const int r   = c0 + rr;
            const float a = g_A[r * NROW + i];
            sBp[rr][col] = pack2(a * g_B[r * NROW + jb + col]);
            sC[rr][col]  = g_C[r * NROW + kb + col];
        }
        __syncthreads();

        #pragma unroll 5
        for (int r = 0; r < CH; r++) {
            const ulonglong2* bp = reinterpret_cast<const ulonglong2*>(&sBp[r][ty * 8]);
            const ulonglong2 b01 = bp[0];
            const ulonglong2 b23 = bp[1];
            const ulonglong2 b45 = bp[2];
            const ulonglong2 b67 = bp[3];
            const ulonglong2* cp = reinterpret_cast<const ulonglong2*>(&sC[r][tx * 8]);
            const ulonglong2 cv0 = cp[0];
            const ulonglong2 cv1 = cp[1];
            unsigned long long bs[8] = {b01.x, b01.y, b23.x, b23.y,
                                        b45.x, b45.y, b67.x, b67.y};
            #pragma unroll
            for (int jj = 0; jj < 8; jj++) {
                acc[jj][0] = ffma2(bs[jj], cv0.x, acc[jj][0]);
                acc[jj][1] = ffma2(bs[jj], cv0.y, acc[jj][1]);
                acc[jj][2] = ffma2(bs[jj], cv1.x, acc[jj][2]);
                acc[jj][3] = ffma2(bs[jj], cv1.y, acc[jj][3]);
            }
        }
        __syncthreads();
    }

    // store: each thread writes 8 rows x 8 cols as 2x float4 per row
    const size_t base = ((size_t)i * NROW + (size_t)(jb + ty * 8)) * NROW
                        + (size_t)(kb + tx * 8);
    #pragma unroll
    for (int jj = 0; jj < 8; jj++) {
        float2 p0 = *reinterpret_cast<float2*>(&acc[jj][0]);
        float2 p1 = *reinterpret_cast<float2*>(&acc[jj][1]);
        float2 p2 = *reinterpret_cast<float2*>(&acc[jj][2]);
        float2 p3 = *reinterpret_cast<float2*>(&acc[jj][3]);
        float4* o = reinterpret_cast<float4*>(out + base + (size_t)jj * NROW);
        o[0] = make_float4(p0.x, p0.y, p1.x, p1.y);
        o[1] = make_float4(p2.x, p2.y, p3.x, p3.y);
    }
}

// ---------------------------------------------------------------------------
// kernel_launch
// ---------------------------------------------------------------------------
extern "C" void kernel_launch(void* const* d_in, const int* in_sizes, int n_in,
                              void* d_out, int out_size)
{
    const float* A_in = (const float*)d_in[0];
    const float* B_in = (const float*)d_in[1];
    const float* C_in = (const float*)d_in[2];
    const float* A_W1 = (const float*)d_in[3];
    const float* A_b1 = (const float*)d_in[4];
    const float* A_W2 = (const float*)d_in[5];
    const float* A_b2 = (const float*)d_in[6];
    const float* B_W1 = (const float*)d_in[7];
    const float* B_b1 = (const float*)d_in[8];
    const float* B_W2 = (const float*)d_in[9];
    const float* B_b2 = (const float*)d_in[10];
    const float* C_W1 = (const float*)d_in[11];
    const float* C_b1 = (const float*)d_in[12];
    const float* C_W2 = (const float*)d_in[13];
    const float* C_b2 = (const float*)d_in[14];
    const float* C_W3 = (const float*)d_in[15];
    const float* C_b3 = (const float*)d_in[16];

    float* out = (float*)d_out;

    transpose_weights<<<(MID * MID + 255) / 256, 256>>>(A_W2, B_W2, C_W2, C_W3);

    factor_kernel<<<NROW, MID>>>(A_in, A_W1, A_b1, A_b2, nullptr, 0, 2);
    factor_kernel<<<NROW, MID>>>(B_in, B_W1, B_b1, B_b2, nullptr, 1, 2);
    factor_kernel<<<NROW, MID>>>(C_in, C_W1, C_b1, C_b2, C_b3, 2, 3);

    dim3 grid(NROW / BN, NROW / BM, NROW);   // (3, 3, 384)
    contract_kernel<<<grid, 256>>>(out);
}

// round 3
// speedup vs baseline: 1.4589x; 1.1455x over previous
#include <cuda_runtime.h>
#include <math.h>

#define OMEGA 1.5f
#define NROW  384
#define MID   256
#define NR    100     // rank R

#define BM 128        // j tile
#define BN 128        // k tile
#define CH 20         // r chunk (100 = 5*20)

// Factor matrices, stored transposed: g_X[r*NROW + row]
__device__ float g_A[NR * NROW];
__device__ float g_B[NR * NROW];
__device__ float g_C[NR * NROW];

// MLP intermediates
__device__ float g_H[3 * NROW * MID];   // first-layer hiddens for nets A,B,C
__device__ float g_H2[NROW * MID];      // C-net second-layer hidden

// ---------------------------------------------------------------------------
// Packed f32x2 helpers
// ---------------------------------------------------------------------------
__device__ __forceinline__ unsigned long long ffma2(unsigned long long a,
                                                    unsigned long long b,
                                                    unsigned long long c) {
    unsigned long long d;
    asm("fma.rn.f32x2 %0, %1, %2, %3;" : "=l"(d) : "l"(a), "l"(b), "l"(c));
    return d;
}
__device__ __forceinline__ unsigned long long pack2(float x) {
    unsigned long long d;
    asm("mov.b64 %0, {%1, %1};" : "=l"(d) : "f"(x));
    return d;
}

// ---------------------------------------------------------------------------
// F1: first sine layer for all 3 nets.  grid (NROW, 3), block MID.
// ---------------------------------------------------------------------------
__global__ void hidden_kernel(const float* __restrict__ Ain,
                              const float* __restrict__ Bin,
                              const float* __restrict__ Cin,
                              const float* __restrict__ AW1, const float* __restrict__ Ab1,
                              const float* __restrict__ BW1, const float* __restrict__ Bb1,
                              const float* __restrict__ CW1, const float* __restrict__ Cb1)
{
    const int net = blockIdx.y;
    const int row = blockIdx.x;
    const int t   = threadIdx.x;
    const float x = (net == 0 ? Ain : net == 1 ? Bin : Cin)[row];
    const float* W1 = (net == 0 ? AW1 : net == 1 ? BW1 : CW1);
    const float* b1 = (net == 0 ? Ab1 : net == 1 ? Bb1 : Cb1);
    g_H[(net * NROW + row) * MID + t] = sinf(OMEGA * (x * W1[t] + b1[t]));
}

// ---------------------------------------------------------------------------
// Tiled GEMM core: acc[4][4] += H[rb+][k] * W[nb+][k], K = MID.
// Block: 256 threads = 16(tx over n) x 16(ty over m). BM=BN=64, BK=32.
// ---------------------------------------------------------------------------
#define BMF 64
#define BNF 64
#define BKF 32

__device__ __forceinline__ void gemm_core(const float* __restrict__ H,
                                          const float* __restrict__ W,
                                          int rb, int nb, int nout,
                                          float acc[4][4])
{
    __shared__ float sH[BMF][BKF + 1];
    __shared__ float sW[BNF][BKF + 1];
    const int tid = threadIdx.x;
    const int kk  = tid & 31;
    const int mm  = tid >> 5;      // 0..7
    const int tx  = tid & 15;
    const int ty  = tid >> 4;
    const int m0  = ty * 4;
    const int n0  = tx * 4;

    #pragma unroll
    for (int i = 0; i < 4; i++)
        #pragma unroll
        for (int j = 0; j < 4; j++) acc[i][j] = 0.f;

    for (int k0 = 0; k0 < MID; k0 += BKF) {
        __syncthreads();
        #pragma unroll
        for (int s = 0; s < 8; s++) {
            const int m = mm + s * 8;
            sH[m][kk] = H[(rb + m) * MID + k0 + kk];
            const int n = nb + m;
            sW[m][kk] = (n < nout) ? W[n * MID + k0 + kk] : 0.f;
        }
        __syncthreads();

        #pragma unroll
        for (int k = 0; k < BKF; k++) {
            float h0 = sH[m0 + 0][k], h1 = sH[m0 + 1][k];
            float h2 = sH[m0 + 2][k], h3 = sH[m0 + 3][k];
            float w0 = sW[n0 + 0][k], w1 = sW[n0 + 1][k];
            float w2 = sW[n0 + 2][k], w3 = sW[n0 + 3][k];
            acc[0][0] += h0 * w0; acc[0][1] += h0 * w1; acc[0][2] += h0 * w2; acc[0][3] += h0 * w3;
            acc[1][0] += h1 * w0; acc[1][1] += h1 * w1; acc[1][2] += h1 * w2; acc[1][3] += h1 * w3;
            acc[2][0] += h2 * w0; acc[2][1] += h2 * w1; acc[2][2] += h2 * w2; acc[2][3] += h2 * w3;
            acc[3][0] += h3 * w0; acc[3][1] += h3 * w1; acc[3][2] += h3 * w2; acc[3][3] += h3 * w3;
        }
    }
}

// F2: C-net middle layer: g_H2 = sin(omega * (g_H[2] @ CW2^T + b2))
// grid (nout/BNF = 4, NROW/BMF = 6), block 256.
__global__ void __launch_bounds__(256) mid_gemm_kernel(const float* __restrict__ CW2,
                                                       const float* __restrict__ Cb2)
{
    const int rb = blockIdx.y * BMF;
    const int nb = blockIdx.x * BNF;
    float acc[4][4];
    gemm_core(g_H + 2 * NROW * MID, CW2, rb, nb, MID, acc);

    const int tx = threadIdx.x & 15, ty = threadIdx.x >> 4;
    #pragma unroll
    for (int i = 0; i < 4; i++) {
        const int m = rb + ty * 4 + i;
        #pragma unroll
        for (int j = 0; j < 4; j++) {
            const int n = nb + tx * 4 + j;
            g_H2[m * MID + n] = sinf(OMEGA * (acc[i][j] + Cb2[n]));
        }
    }
}

// F3: final layers for all three nets -> transposed factor matrices.
// grid (2, NROW/BMF = 6, 3), block 256.
__global__ void __launch_bounds__(256) final_gemm_kernel(const float* __restrict__ AW2,
                                                         const float* __restrict__ Ab2,
                                                         const float* __restrict__ BW2,
                                                         const float* __restrict__ Bb2,
                                                         const float* __restrict__ CW3,
                                                         const float* __restrict__ Cb3)
{
    const int net = blockIdx.z;
    const int rb  = blockIdx.y * BMF;
    const int nb  = blockIdx.x * BNF;
    const float* H = (net == 2) ? g_H2 : g_H + net * NROW * MID;
    const float* W = (net == 0) ? AW2 : (net == 1) ? BW2 : CW3;
    const float* b = (net == 0) ? Ab2 : (net == 1) ? Bb2 : Cb3;
    float* out     = (net == 0) ? g_A : (net == 1) ? g_B : g_C;

    float acc[4][4];
    gemm_core(H, W, rb, nb, NR, acc);

    const int tx = threadIdx.x & 15, ty = threadIdx.x >> 4;
    #pragma unroll
    for (int i = 0; i < 4; i++) {
        const int m = rb + ty * 4 + i;
        #pragma unroll
        for (int j = 0; j < 4; j++) {
            const int n = nb + tx * 4 + j;
            if (n < NR) out[n * NROW + m] = acc[i][j] + b[n];
        }
    }
}

// ---------------------------------------------------------------------------
// Contraction: out[i,j,k] = sum_r A[i,r]*B[j,r]*C[k,r]
// Grid: (3, 3, 384). Block 256 = 16(tx:k) x 16(ty:j). 8x8 micro-tile / thread.
// Software-pipelined: next chunk's globals prefetched into regs during compute.
// ---------------------------------------------------------------------------
__global__ void __launch_bounds__(256, 2) contract_kernel(float* __restrict__ out)
{
    const int i  = blockIdx.z;
    const int jb = blockIdx.y * BM;
    const int kb = blockIdx.x * BN;
    const int tid = threadIdx.x;
    const int tx = tid & 15;   // k octet index
    const int ty = tid >> 4;   // j octet index
    const int col = tid & 127;
    const int hi  = tid >> 7;  // 0 or 1

    __shared__ alignas(16) unsigned long long sBp[CH][BM];  // packed A[i,r]*B[j,r]
    __shared__ alignas(16) float sC[CH][BN];                // C[k,r]

    unsigned long long acc[8][4];
    #pragma unroll
    for (int a = 0; a < 8; a++)
        #pragma unroll
        for (int b = 0; b < 4; b++) acc[a][b] = 0ull;

    float pb[10], pc[10];   // prefetch regs (A folded into pb)

    // prefetch chunk 0
    #pragma unroll
    for (int n = 0; n < 10; n++) {
        const int r = 2 * n + hi;
        pb[n] = g_A[r * NROW + i] * g_B[r * NROW + jb + col];
        pc[n] = g_C[r * NROW + kb + col];
    }

    for (int c = 0; c < 5; c++) {
        if (c) __syncthreads();            // previous chunk fully consumed
        #pragma unroll
        for (int n = 0; n < 10; n++) {
            sBp[2 * n + hi][col] = pack2(pb[n]);
            sC [2 * n + hi][col] = pc[n];
        }
        __syncthreads();

        if (c < 4) {                       // prefetch next chunk (overlaps FFMAs)
            const int c0 = (c + 1) * CH;
            #pragma unroll
            for (int n = 0; n < 10; n++) {
                const int r = c0 + 2 * n + hi;
                pb[n] = g_A[r * NROW + i] * g_B[r * NROW + jb + col];
                pc[n] = g_C[r * NROW + kb + col];
            }
        }

        #pragma unroll
        for (int r = 0; r < CH; r++) {
            const ulonglong2* bp = reinterpret_cast<const ulonglong2*>(&sBp[r][ty * 8]);
            const ulonglong2 b01 = bp[0];
            const ulonglong2 b23 = bp[1];
            const ulonglong2 b45 = bp[2];
            const ulonglong2 b67 = bp[3];
            const ulonglong2* cp = reinterpret_cast<const ulonglong2*>(&sC[r][tx * 8]);
            const ulonglong2 cv0 = cp[0];
            const ulonglong2 cv1 = cp[1];
            unsigned long long bs[8] = {b01.x, b01.y, b23.x, b23.y,
                                        b45.x, b45.y, b67.x, b67.y};
            #pragma unroll
            for (int jj = 0; jj < 8; jj++) {
                acc[jj][0] = ffma2(bs[jj], cv0.x, acc[jj][0]);
                acc[jj][1] = ffma2(bs[jj], cv0.y, acc[jj][1]);
                acc[jj][2] = ffma2(bs[jj], cv1.x, acc[jj][2]);
                acc[jj][3] = ffma2(bs[jj], cv1.y, acc[jj][3]);
            }
        }
    }

    // store: each thread writes 8 rows x 8 cols as 2x float4 per row
    const size_t base = ((size_t)i * NROW + (size_t)(jb + ty * 8)) * NROW
                        + (size_t)(kb + tx * 8);
    #pragma unroll
    for (int jj = 0; jj < 8; jj++) {
        float2 p0 = *reinterpret_cast<float2*>(&acc[jj][0]);
        float2 p1 = *reinterpret_cast<float2*>(&acc[jj][1]);
        float2 p2 = *reinterpret_cast<float2*>(&acc[jj][2]);
        float2 p3 = *reinterpret_cast<float2*>(&acc[jj][3]);
        float4* o = reinterpret_cast<float4*>(out + base + (size_t)jj * NROW);
        o[0] = make_float4(p0.x, p0.y, p1.x, p1.y);
        o[1] = make_float4(p2.x, p2.y, p3.x, p3.y);
    }
}

// ---------------------------------------------------------------------------
// kernel_launch
// ---------------------------------------------------------------------------
extern "C" void kernel_launch(void* const* d_in, const int* in_sizes, int n_in,
                              void* d_out, int out_size)
{
    const float* A_in = (const float*)d_in[0];
    const float* B_in = (const float*)d_in[1];
    const float* C_in = (const float*)d_in[2];
    const float* A_W1 = (const float*)d_in[3];
    const float* A_b1 = (const float*)d_in[4];
    const float* A_W2 = (const float*)d_in[5];
    const float* A_b2 = (const float*)d_in[6];
    const float* B_W1 = (const float*)d_in[7];
    const float* B_b1 = (const float*)d_in[8];
    const float* B_W2 = (const float*)d_in[9];
    const float* B_b2 = (const float*)d_in[10];
    const float* C_W1 = (const float*)d_in[11];
    const float* C_b1 = (const float*)d_in[12];
    const float* C_W2 = (const float*)d_in[13];
    const float* C_b2 = (const float*)d_in[14];
    const float* C_W3 = (const float*)d_in[15];
    const float* C_b3 = (const float*)d_in[16];

    float* out = (float*)d_out;

    dim3 g1(NROW, 3);
    hidden_kernel<<<g1, MID>>>(A_in, B_in, C_in, A_W1, A_b1, B_W1, B_b1, C_W1, C_b1);

    dim3 g2(MID / BNF, NROW / BMF);          // (4, 6)
    mid_gemm_kernel<<<g2, 256>>>(C_W2, C_b2);

    dim3 g3((NR + BNF - 1) / BNF, NROW / BMF, 3);   // (2, 6, 3)
    final_gemm_kernel<<<g3, 256>>>(A_W2, A_b2, B_W2, B_b2, C_W3, C_b3);

    dim3 grid(NROW / BN, NROW / BM, NROW);   // (3, 3, 384)
    contract_kernel<<<grid, 256>>>(out);
}

// round 5
// speedup vs baseline: 2.2974x; 1.5748x over previous
#include <cuda_runtime.h>
#include <cuda_bf16.h>
#include <math.h>
#include <stdint.h>

#define OMEGA 1.5f
#define NROW  384
#define MID   256
#define NR    100     // rank R
#define RP    128     // padded rank (K dim for MMA)

// Factor matrices, row-major padded K: g_X[row*RP + r], r<100 valid, rest 0
__device__ float g_A[NROW * RP];
__device__ float g_B[NROW * RP];
__device__ __nv_bfloat16 g_Chi[NROW * RP];   // C split hi
__device__ __nv_bfloat16 g_Clo[NROW * RP];   // C split lo

// MLP intermediates
__device__ float g_H[3 * NROW * MID];
__device__ float g_H2[NROW * MID];

// ===========================================================================
// helpers
// ===========================================================================
__device__ __forceinline__ uint32_t smem_u32(const void* p) {
    uint32_t a;
    asm("{ .reg .u64 t; cvta.to.shared.u64 t, %1; cvt.u32.u64 %0, t; }" : "=r"(a) : "l"(p));
    return a;
}
__device__ __forceinline__ void ldsm4(uint32_t addr, uint32_t r[4]) {
    asm volatile("ldmatrix.sync.aligned.m8n8.x4.shared.b16 {%0,%1,%2,%3}, [%4];"
                 : "=r"(r[0]), "=r"(r[1]), "=r"(r[2]), "=r"(r[3]) : "r"(addr));
}
__device__ __forceinline__ void mma16816(float d[4], const uint32_t a[4],
                                         uint32_t b0, uint32_t b1) {
    asm volatile("mma.sync.aligned.m16n8k16.row.col.f32.bf16.bf16.f32 "
                 "{%0,%1,%2,%3}, {%4,%5,%6,%7}, {%8,%9}, {%0,%1,%2,%3};"
                 : "+f"(d[0]), "+f"(d[1]), "+f"(d[2]), "+f"(d[3])
                 : "r"(a[0]), "r"(a[1]), "r"(a[2]), "r"(a[3]), "r"(b0), "r"(b1));
}
__device__ __forceinline__ void split2(float x0, float x1, uint32_t& hi, uint32_t& lo) {
    __nv_bfloat16 h0 = __float2bfloat16(x0);
    __nv_bfloat16 h1 = __float2bfloat16(x1);
    __nv_bfloat16 l0 = __float2bfloat16(x0 - __bfloat162float(h0));
    __nv_bfloat16 l1 = __float2bfloat16(x1 - __bfloat162float(h1));
    hi = (uint32_t)__bfloat16_as_ushort(h0) | ((uint32_t)__bfloat16_as_ushort(h1) << 16);
    lo = (uint32_t)__bfloat16_as_ushort(l0) | ((uint32_t)__bfloat16_as_ushort(l1) << 16);
}

// ===========================================================================
// Factor networks (structure from R3; C-net epilogue writes bf16 hi/lo split)
// ===========================================================================
__global__ void hidden_kernel(const float* __restrict__ Ain,
                              const float* __restrict__ Bin,
                              const float* __restrict__ Cin,
                              const float* __restrict__ AW1, const float* __restrict__ Ab1,
                              const float* __restrict__ BW1, const float* __restrict__ Bb1,
                              const float* __restrict__ CW1, const float* __restrict__ Cb1)
{
    const int net = blockIdx.y;
    const int row = blockIdx.x;
    const int t   = threadIdx.x;
    const float x = (net == 0 ? Ain : net == 1 ? Bin : Cin)[row];
    const float* W1 = (net == 0 ? AW1 : net == 1 ? BW1 : CW1);
    const float* b1 = (net == 0 ? Ab1 : net == 1 ? Bb1 : Cb1);
    g_H[(net * NROW + row) * MID + t] = sinf(OMEGA * (x * W1[t] + b1[t]));
}

#define BMF 64
#define BNF 64
#define BKF 32

__device__ __forceinline__ void gemm_core(const float* __restrict__ H,
                                          const float* __restrict__ W,
                                          int rb, int nb, int nout,
                                          float acc[4][4])
{
    __shared__ float sH[BMF][BKF + 1];
    __shared__ float sW[BNF][BKF + 1];
    const int tid = threadIdx.x;
    const int kk  = tid & 31;
    const int mm  = tid >> 5;
    const int tx  = tid & 15;
    const int ty  = tid >> 4;
    const int m0  = ty * 4;
    const int n0  = tx * 4;

    #pragma unroll
    for (int i = 0; i < 4; i++)
        #pragma unroll
        for (int j = 0; j < 4; j++) acc[i][j] = 0.f;

    for (int k0 = 0; k0 < MID; k0 += BKF) {
        __syncthreads();
        #pragma unroll
        for (int s = 0; s < 8; s++) {
            const int m = mm + s * 8;
            sH[m][kk] = H[(rb + m) * MID + k0 + kk];
            const int n = nb + m;
            sW[m][kk] = (n < nout) ? W[n * MID + k0 + kk] : 0.f;
        }
        __syncthreads();
        #pragma unroll
        for (int k = 0; k < BKF; k++) {
            float h0 = sH[m0 + 0][k], h1 = sH[m0 + 1][k];
            float h2 = sH[m0 + 2][k], h3 = sH[m0 + 3][k];
            float w0 = sW[n0 + 0][k], w1 = sW[n0 + 1][k];
            float w2 = sW[n0 + 2][k], w3 = sW[n0 + 3][k];
            acc[0][0] += h0 * w0; acc[0][1] += h0 * w1; acc[0][2] += h0 * w2; acc[0][3] += h0 * w3;
            acc[1][0] += h1 * w0; acc[1][1] += h1 * w1; acc[1][2] += h1 * w2; acc[1][3] += h1 * w3;
            acc[2][0] += h2 * w0; acc[2][1] += h2 * w1; acc[2][2] += h2 * w2; acc[2][3] += h2 * w3;
            acc[3][0] += h3 * w0; acc[3][1] += h3 * w1; acc[3][2] += h3 * w2; acc[3][3] += h3 * w3;
        }
    }
}

__global__ void __launch_bounds__(256) mid_gemm_kernel(const float* __restrict__ CW2,
                                                       const float* __restrict__ Cb2)
{
    const int rb = blockIdx.y * BMF;
    const int nb = blockIdx.x * BNF;
    float acc[4][4];
    gemm_core(g_H + 2 * NROW * MID, CW2, rb, nb, MID, acc);
    const int tx = threadIdx.x & 15, ty = threadIdx.x >> 4;
    #pragma unroll
    for (int i = 0; i < 4; i++) {
        const int m = rb + ty * 4 + i;
        #pragma unroll
        for (int j = 0; j < 4; j++) {
            const int n = nb + tx * 4 + j;
            g_H2[m * MID + n] = sinf(OMEGA * (acc[i][j] + Cb2[n]));
        }
    }
}

__global__ void __launch_bounds__(256) final_gemm_kernel(const float* __restrict__ AW2,
                                                         const float* __restrict__ Ab2,
                                                         const float* __restrict__ BW2,
                                                         const float* __restrict__ Bb2,
                                                         const float* __restrict__ CW3,
                                                         const float* __restrict__ Cb3)
{
    const int net = blockIdx.z;
    const int rb  = blockIdx.y * BMF;
    const int nb  = blockIdx.x * BNF;
    const float* H = (net == 2) ? g_H2 : g_H + net * NROW * MID;
    const float* W = (net == 0) ? AW2 : (net == 1) ? BW2 : CW3;
    const float* b = (net == 0) ? Ab2 : (net == 1) ? Bb2 : Cb3;

    float acc[4][4];
    gemm_core(H, W, rb, nb, NR, acc);
    const int tx = threadIdx.x & 15, ty = threadIdx.x >> 4;
    #pragma unroll
    for (int i = 0; i < 4; i++) {
        const int m = rb + ty * 4 + i;
        #pragma unroll
        for (int j = 0; j < 4; j++) {
            const int n = nb + tx * 4 + j;
            if (n < NR) {
                const float v = acc[i][j] + b[n];
                if (net == 0)      g_A[m * RP + n] = v;
                else if (net == 1) g_B[m * RP + n] = v;
                else {
                    __nv_bfloat16 h = __float2bfloat16(v);
                    g_Chi[m * RP + n] = h;
                    g_Clo[m * RP + n] = __float2bfloat16(v - __bfloat162float(h));
                }
            }
        }
    }
}

// ===========================================================================
// Contraction via mma.sync (HMMA) bf16 3-pass split.
// CTA = (jb, i). Block 256 = 8 warps, warp tile 32(m=j) x 64(n=k).
// SMEM: Mhi/Mlo [128x128] bf16 stride 136; C double-buffered hi/lo tiles.
// ===========================================================================
#define LDE 136
#define LDB 272                      // bytes per smem row
#define MT_BYTES (128 * LDB)         // 34816 per tile
#define OFF_MHI 0
#define OFF_MLO MT_BYTES
#define OFF_C   (2 * MT_BYTES)       // 4 tiles: buf0{hi,lo}, buf1{hi,lo}
#define SMEM_NEED (6 * MT_BYTES)     // 208896 bytes

__device__ __forceinline__ void copy_C(char* sm, uint32_t off, int kt, int tid) {
    #pragma unroll
    for (int it = 0; it < 16; it++) {
        const int idx = tid + it * 256;          // 0..4095
        const int arr = idx >> 11;               // 0=hi, 1=lo
        const int e   = idx & 2047;
        const int row = e >> 4;
        const int col = e & 15;
        const __nv_bfloat16* src = (arr ? g_Clo : g_Chi) + (kt * 128 + row) * RP + col * 8;
        const uint4 v = *reinterpret_cast<const uint4*>(src);
        *reinterpret_cast<uint4*>(sm + off + arr * MT_BYTES + row * LDB + col * 16) = v;
    }
}

__global__ void __launch_bounds__(256, 1) contract_kernel(float* __restrict__ out)
{
    extern __shared__ __align__(16) char sm[];
    const uint32_t sbase = smem_u32(sm);

    const int tid  = threadIdx.x;
    const int lane = tid & 31;
    const int wid  = tid >> 5;
    const int i    = blockIdx.y;
    const int jb   = blockIdx.x * 128;

    const int wm = (wid & 3) * 32;    // m (j) offset of warp
    const int wn = (wid >> 2) * 64;   // n (k) offset of warp

    // ---- convert M = A[i,:] * B[jb:,:] into hi/lo, and copy C tile 0 ----
    #pragma unroll 4
    for (int it = 0; it < 32; it++) {
        const int idx = tid + it * 256;
        const int j = idx >> 6, pr = idx & 63;
        const int r0 = pr * 2;
        float2 bv = make_float2(0.f, 0.f);
        float2 av = make_float2(0.f, 0.f);
        if (pr < 50) {
            bv = *reinterpret_cast<const float2*>(&g_B[(jb + j) * RP + r0]);
            av = *reinterpret_cast<const float2*>(&g_A[i * RP + r0]);
        }
        uint32_t hi, lo;
        split2(av.x * bv.x, av.y * bv.y, hi, lo);
        const uint32_t off = (uint32_t)(j * LDB + pr * 4);
        *reinterpret_cast<uint32_t*>(sm + OFF_MHI + off) = hi;
        *reinterpret_cast<uint32_t*>(sm + OFF_MLO + off) = lo;
    }
    copy_C(sm, OFF_C, 0, tid);
    __syncthreads();

    // fragment lane offsets
    const uint32_t aoff = (uint32_t)((lane & 15) * LDB + (lane >> 4) * 16);
    const uint32_t boff = (uint32_t)(((lane & 7) + ((lane >> 4) << 3)) * LDB
                                     + ((lane >> 3) & 1) * 16);
    const uint32_t mhiA = sbase + OFF_MHI + (uint32_t)(wm * LDB) + aoff;
    const uint32_t mloA = sbase + OFF_MLO + (uint32_t)(wm * LDB) + aoff;

    float acc[16][4];
    #pragma unroll
    for (int t = 0; t < 16; t++)
        #pragma unroll
        for (int q = 0; q < 4; q++) acc[t][q] = 0.f;

    const int g  = lane >> 2;
    const int c2 = (lane & 3) * 2;

    for (int kb = 0; kb < 3; kb++) {
        if (kb < 2) copy_C(sm, OFF_C + (uint32_t)(((kb + 1) & 1) * 2 * MT_BYTES), kb + 1, tid);

        const uint32_t cbuf = sbase + OFF_C + (uint32_t)((kb & 1) * 2 * MT_BYTES);

        #pragma unroll
        for (int pass = 0; pass < 3; pass++) {
            const uint32_t Ab = (pass == 2) ? mloA : mhiA;
            const uint32_t Bb = cbuf + ((pass == 1) ? (uint32_t)MT_BYTES : 0u)
                               + (uint32_t)(wn * LDB) + boff;
            #pragma unroll
            for (int ks = 0; ks < 8; ks++) {
                uint32_t a0[4], a1[4];
                ldsm4(Ab + ks * 32, a0);
                ldsm4(Ab + 16 * LDB + ks * 32, a1);
                uint32_t bb[16];
                #pragma unroll
                for (int p = 0; p < 4; p++)
                    ldsm4(Bb + (uint32_t)(p * 16 * LDB) + ks * 32, bb + 4 * p);
                #pragma unroll
                for (int nt = 0; nt < 8; nt++) {
                    const uint32_t b0 = bb[(nt >> 1) * 4 + (nt & 1) * 2];
                    const uint32_t b1 = bb[(nt >> 1) * 4 + (nt & 1) * 2 + 1];
                    mma16816(acc[nt], a0, b0, b1);
                    mma16816(acc[8 + nt], a1, b0, b1);
                }
            }
        }

        // store this k-tile and reset acc
        #pragma unroll
        for (int mt = 0; mt < 2; mt++) {
            #pragma unroll
            for (int nt = 0; nt < 8; nt++) {
                float* p = out + ((size_t)i * NROW + (size_t)(jb + wm + mt * 16 + g)) * NROW
                               + (size_t)(kb * 128 + wn + nt * 8 + c2);
                *reinterpret_cast<float2*>(p) = make_float2(acc[mt * 8 + nt][0], acc[mt * 8 + nt][1]);
                *reinterpret_cast<float2*>(p + (size_t)8 * NROW) =
                    make_float2(acc[mt * 8 + nt][2], acc[mt * 8 + nt][3]);
                acc[mt * 8 + nt][0] = 0.f; acc[mt * 8 + nt][1] = 0.f;
                acc[mt * 8 + nt][2] = 0.f; acc[mt * 8 + nt][3] = 0.f;
            }
        }
        __syncthreads();
    }
}

// ===========================================================================
// kernel_launch
// ===========================================================================
extern "C" void kernel_launch(void* const* d_in, const int* in_sizes, int n_in,
                              void* d_out, int out_size)
{
    const float* A_in = (const float*)d_in[0];
    const float* B_in = (const float*)d_in[1];
    const float* C_in = (const float*)d_in[2];
    const float* A_W1 = (const float*)d_in[3];
    const float* A_b1 = (const float*)d_in[4];
    const float* A_W2 = (const float*)d_in[5];
    const float* A_b2 = (const float*)d_in[6];
    const float* B_W1 = (const float*)d_in[7];
    const float* B_b1 = (const float*)d_in[8];
    const float* B_W2 = (const float*)d_in[9];
    const float* B_b2 = (const float*)d_in[10];
    const float* C_W1 = (const float*)d_in[11];
    const float* C_b1 = (const float*)d_in[12];
    const float* C_W2 = (const float*)d_in[13];
    const float* C_b2 = (const float*)d_in[14];
    const float* C_W3 = (const float*)d_in[15];
    const float* C_b3 = (const float*)d_in[16];

    float* out = (float*)d_out;

    cudaFuncSetAttribute(contract_kernel,
                         cudaFuncAttributeMaxDynamicSharedMemorySize, SMEM_NEED);

    dim3 g1(NROW, 3);
    hidden_kernel<<<g1, MID>>>(A_in, B_in, C_in, A_W1, A_b1, B_W1, B_b1, C_W1, C_b1);

    dim3 g2(MID / BNF, NROW / BMF);
    mid_gemm_kernel<<<g2, 256>>>(C_W2, C_b2);

    dim3 g3((NR + BNF - 1) / BNF, NROW / BMF, 3);
    final_gemm_kernel<<<g3, 256>>>(A_W2, A_b2, B_W2, B_b2, C_W3, C_b3);

    dim3 grid(NROW / 128, NROW);   // (3 j-tiles, 384 i)
    contract_kernel<<<grid, 256, SMEM_NEED>>>(out);
}

// round 7
// speedup vs baseline: 2.8070x; 1.2218x over previous
#include <cuda_runtime.h>
#include <cuda_bf16.h>
#include <math.h>
#include <stdint.h>

#define OMEGA 1.5f
#define NROW  384
#define MID   256
#define NR    100     // rank R
#define RP    112     // padded rank (K dim for MMA), 7 x k16

// Factor matrices, row-major padded K: g_X[row*RP + r], r<100 valid, rest 0
__device__ float g_A[NROW * RP];
__device__ float g_B[NROW * RP];
__device__ __nv_bfloat16 g_Chi[NROW * RP];   // C split hi
__device__ __nv_bfloat16 g_Clo[NROW * RP];   // C split lo

// MLP intermediates
__device__ float g_H[3 * NROW * MID];
__device__ float g_H2[NROW * MID];

// ===========================================================================
// helpers
// ===========================================================================
__device__ __forceinline__ uint32_t smem_u32(const void* p) {
    uint32_t a;
    asm("{ .reg .u64 t; cvta.to.shared.u64 t, %1; cvt.u32.u64 %0, t; }" : "=r"(a) : "l"(p));
    return a;
}
__device__ __forceinline__ void ldsm4(uint32_t addr, uint32_t r[4]) {
    asm volatile("ldmatrix.sync.aligned.m8n8.x4.shared.b16 {%0,%1,%2,%3}, [%4];"
                 : "=r"(r[0]), "=r"(r[1]), "=r"(r[2]), "=r"(r[3]) : "r"(addr));
}
__device__ __forceinline__ void mma16816(float d[4], const uint32_t a[4],
                                         uint32_t b0, uint32_t b1) {
    asm volatile("mma.sync.aligned.m16n8k16.row.col.f32.bf16.bf16.f32 "
                 "{%0,%1,%2,%3}, {%4,%5,%6,%7}, {%8,%9}, {%0,%1,%2,%3};"
                 : "+f"(d[0]), "+f"(d[1]), "+f"(d[2]), "+f"(d[3])
                 : "r"(a[0]), "r"(a[1]), "r"(a[2]), "r"(a[3]), "r"(b0), "r"(b1));
}
__device__ __forceinline__ void split2(float x0, float x1, uint32_t& hi, uint32_t& lo) {
    __nv_bfloat16 h0 = __float2bfloat16(x0);
    __nv_bfloat16 h1 = __float2bfloat16(x1);
    __nv_bfloat16 l0 = __float2bfloat16(x0 - __bfloat162float(h0));
    __nv_bfloat16 l1 = __float2bfloat16(x1 - __bfloat162float(h1));
    hi = (uint32_t)__bfloat16_as_ushort(h0) | ((uint32_t)__bfloat16_as_ushort(h1) << 16);
    lo = (uint32_t)__bfloat16_as_ushort(l0) | ((uint32_t)__bfloat16_as_ushort(l1) << 16);
}
__device__ __forceinline__ void cp16(uint32_t dst, const void* src) {
    asm volatile("cp.async.cg.shared.global [%0], [%1], 16;" :: "r"(dst), "l"(src));
}
#define CP_COMMIT() asm volatile("cp.async.commit_group;" ::: "memory")
#define CP_WAIT0()  asm volatile("cp.async.wait_group 0;" ::: "memory")

// ===========================================================================
// Factor networks
// ===========================================================================
__global__ void hidden_kernel(const float* __restrict__ Ain,
                              const float* __restrict__ Bin,
                              const float* __restrict__ Cin,
                              const float* __restrict__ AW1, const float* __restrict__ Ab1,
                              const float* __restrict__ BW1, const float* __restrict__ Bb1,
                              const float* __restrict__ CW1, const float* __restrict__ Cb1)
{
    const int net = blockIdx.y;
    const int row = blockIdx.x;
    const int t   = threadIdx.x;
    const float x = (net == 0 ? Ain : net == 1 ? Bin : Cin)[row];
    const float* W1 = (net == 0 ? AW1 : net == 1 ? BW1 : CW1);
    const float* b1 = (net == 0 ? Ab1 : net == 1 ? Bb1 : Cb1);
    g_H[(net * NROW + row) * MID + t] = sinf(OMEGA * (x * W1[t] + b1[t]));
}

// 32x32 tile GEMM core, 256 threads, micro 2x2.
__device__ __forceinline__ void gemm32(const float* __restrict__ H,
                                       const float* __restrict__ W,
                                       int rb, int nb, int nout,
                                       float acc[2][2])
{
    __shared__ float sH[32][33];
    __shared__ float sW[32][33];
    const int tid = threadIdx.x;
    const int kk  = tid & 31;
    const int mm  = tid >> 5;        // 0..7
    const int tx  = tid & 15;
    const int ty  = tid >> 4;
    const int m0  = ty * 2;
    const int n0  = tx * 2;

    acc[0][0] = acc[0][1] = acc[1][0] = acc[1][1] = 0.f;

    for (int k0 = 0; k0 < MID; k0 += 32) {
        __syncthreads();
        #pragma unroll
        for (int s = 0; s < 4; s++) {
            const int r = mm + s * 8;
            sH[r][kk] = H[(rb + r) * MID + k0 + kk];
            const int n = nb + r;
            sW[r][kk] = (n < nout) ? W[n * MID + k0 + kk] : 0.f;
        }
        __syncthreads();
        #pragma unroll
        for (int k = 0; k < 32; k++) {
            const float h0 = sH[m0][k], h1 = sH[m0 + 1][k];
            const float w0 = sW[n0][k], w1 = sW[n0 + 1][k];
            acc[0][0] += h0 * w0; acc[0][1] += h0 * w1;
            acc[1][0] += h1 * w0; acc[1][1] += h1 * w1;
        }
    }
}

__global__ void __launch_bounds__(256) mid_gemm_kernel(const float* __restrict__ CW2,
                                                       const float* __restrict__ Cb2)
{
    const int rb = blockIdx.y * 32;
    const int nb = blockIdx.x * 32;
    float acc[2][2];
    gemm32(g_H + 2 * NROW * MID, CW2, rb, nb, MID, acc);
    const int tx = threadIdx.x & 15, ty = threadIdx.x >> 4;
    #pragma unroll
    for (int i = 0; i < 2; i++) {
        const int m = rb + ty * 2 + i;
        #pragma unroll
        for (int j = 0; j < 2; j++) {
            const int n = nb + tx * 2 + j;
            g_H2[m * MID + n] = sinf(OMEGA * (acc[i][j] + Cb2[n]));
        }
    }
}

__global__ void __launch_bounds__(256) final_gemm_kernel(const float* __restrict__ AW2,
                                                         const float* __restrict__ Ab2,
                                                         const float* __restrict__ BW2,
                                                         const float* __restrict__ Bb2,
                                                         const float* __restrict__ CW3,
                                                         const float* __restrict__ Cb3)
{
    const int net = blockIdx.z;
    const int rb  = blockIdx.y * 32;
    const int nb  = blockIdx.x * 32;
    const float* H = (net == 2) ? g_H2 : g_H + net * NROW * MID;
    const float* W = (net == 0) ? AW2 : (net == 1) ? BW2 : CW3;
    const float* b = (net == 0) ? Ab2 : (net == 1) ? Bb2 : Cb3;

    float acc[2][2];
    gemm32(H, W, rb, nb, NR, acc);
    const int tx = threadIdx.x & 15, ty = threadIdx.x >> 4;
    #pragma unroll
    for (int i = 0; i < 2; i++) {
        const int m = rb + ty * 2 + i;
        #pragma unroll
        for (int j = 0; j < 2; j++) {
            const int n = nb + tx * 2 + j;
            if (n < NR) {
                const float v = acc[i][j] + b[n];
                if (net == 0)      g_A[m * RP + n] = v;
                else if (net == 1) g_B[m * RP + n] = v;
                else {
                    __nv_bfloat16 h = __float2bfloat16(v);
                    g_Chi[m * RP + n] = h;
                    g_Clo[m * RP + n] = __float2bfloat16(v - __bfloat162float(h));
                }
            }
        }
    }
}

// ===========================================================================
// Contraction via HMMA bf16 3-pass split. Block 512 = 16 warps (4m x 4n),
// warp tile 32(j) x 32(k). CTA = (jb, i), covers 128j x 384k (3 kb iters).
// K = 112 (7 k16 steps). SMEM row stride 240B.
// C tiles pre-split bf16 in global, streamed via cp.async, double-buffered.
// ===========================================================================
#define LDB 240
#define MT  (128 * LDB)              // 30720 bytes per [128 x 112] bf16 tile
#define OFF_MHI 0
#define OFF_MLO MT
#define OFF_C   (2 * MT)             // buf b at OFF_C + b*2*MT: {hi, lo}
#define SMEM_NEED (6 * MT)           // 184320 bytes

#define C_CHUNKS 1792                // 128 rows x 14 chunks of 16B per array

__device__ __forceinline__ void prefetch_C(uint32_t sb, int kt, int buf, int tid) {
    const uint32_t dst0 = sb + OFF_C + (uint32_t)(buf * 2 * MT);
    #pragma unroll
    for (int it = 0; it < 7; it++) {
        const int idx = tid + it * 512;          // 0..3583 = 2*1792
        const int arr = (idx >= C_CHUNKS) ? 1 : 0;   // 0=hi, 1=lo
        const int e   = idx - arr * C_CHUNKS;
        const int row = e / 14;
        const int ch  = e % 14;
        const __nv_bfloat16* src = (arr ? g_Clo : g_Chi) + (kt * 128 + row) * RP + ch * 8;
        cp16(dst0 + (uint32_t)(arr * MT + row * LDB + ch * 16), src);
    }
}

__global__ void __launch_bounds__(512, 1) contract_kernel(float* __restrict__ out)
{
    extern __shared__ __align__(16) char sm[];
    const uint32_t sbase = smem_u32(sm);

    const int tid  = threadIdx.x;
    const int lane = tid & 31;
    const int wid  = tid >> 5;
    const int i    = blockIdx.y;
    const int jb   = blockIdx.x * 128;

    const int wm = (wid & 3) * 32;    // m (j) offset
    const int wn = (wid >> 2) * 32;   // n (k) offset within kb tile

    // prefetch C tile 0, then convert M = A[i,:] * B[jb:,:] into hi/lo
    prefetch_C(sbase, 0, 0, tid);
    CP_COMMIT();

    #pragma unroll
    for (int it = 0; it < 14; it++) {
        const int idx = tid + it * 512;          // 0..7167 = 128 x 56
        const int j  = idx / 56;
        const int pr = idx % 56;
        const int r0 = pr * 2;
        float2 bv = make_float2(0.f, 0.f), av = make_float2(0.f, 0.f);
        if (pr < 50) {
            bv = *reinterpret_cast<const float2*>(&g_B[(jb + j) * RP + r0]);
            av = *reinterpret_cast<const float2*>(&g_A[i * RP + r0]);
        }
        uint32_t hi, lo;
        split2(av.x * bv.x, av.y * bv.y, hi, lo);
        const uint32_t off = (uint32_t)(j * LDB + pr * 4);
        *reinterpret_cast<uint32_t*>(sm + OFF_MHI + off) = hi;
        *reinterpret_cast<uint32_t*>(sm + OFF_MLO + off) = lo;
    }
    CP_WAIT0();
    __syncthreads();

    // fragment lane addresses
    const uint32_t aoff = (uint32_t)((lane & 15) * LDB + (lane >> 4) * 16);
    const uint32_t boff = (uint32_t)(((lane & 7) + ((lane >> 4) << 3)) * LDB
                                     + ((lane >> 3) & 1) * 16);
    const uint32_t mhiA = sbase + OFF_MHI + (uint32_t)(wm * LDB) + aoff;
    const uint32_t mloA = sbase + OFF_MLO + (uint32_t)(wm * LDB) + aoff;

    float acc[8][4];
    #pragma unroll
    for (int t = 0; t < 8; t++)
        #pragma unroll
        for (int q = 0; q < 4; q++) acc[t][q] = 0.f;

    const int g  = lane >> 2;
    const int c2 = (lane & 3) * 2;

    for (int kb = 0; kb < 3; kb++) {
        if (kb < 2) { prefetch_C(sbase, kb + 1, (kb + 1) & 1, tid); CP_COMMIT(); }

        const uint32_t cbuf = sbase + OFF_C + (uint32_t)((kb & 1) * 2 * MT);

        #pragma unroll
        for (int pass = 0; pass < 3; pass++) {
            const uint32_t Ab = (pass == 2) ? mloA : mhiA;
            const uint32_t Bb = cbuf + ((pass == 1) ? (uint32_t)MT : 0u)
                               + (uint32_t)(wn * LDB) + boff;
            #pragma unroll
            for (int ks = 0; ks < 7; ks++) {
                uint32_t a0[4], a1[4];
                ldsm4(Ab + ks * 32, a0);
                ldsm4(Ab + 16 * LDB + ks * 32, a1);
                uint32_t bb[8];
                ldsm4(Bb + ks * 32, bb);
                ldsm4(Bb + 16 * LDB + ks * 32, bb + 4);
                #pragma unroll
                for (int nt = 0; nt < 4; nt++) {
                    const uint32_t b0 = bb[(nt >> 1) * 4 + (nt & 1) * 2];
                    const uint32_t b1 = bb[(nt >> 1) * 4 + (nt & 1) * 2 + 1];
                    mma16816(acc[nt], a0, b0, b1);
                    mma16816(acc[4 + nt], a1, b0, b1);
                }
            }
        }

        // store this k-tile, reset acc
        #pragma unroll
        for (int mt = 0; mt < 2; mt++) {
            #pragma unroll
            for (int nt = 0; nt < 4; nt++) {
                float* p = out + ((size_t)i * NROW + (size_t)(jb + wm + mt * 16 + g)) * NROW
                               + (size_t)(kb * 128 + wn + nt * 8 + c2);
                float* a = acc[mt * 4 + nt];
                *reinterpret_cast<float2*>(p) = make_float2(a[0], a[1]);
                *reinterpret_cast<float2*>(p + (size_t)8 * NROW) = make_float2(a[2], a[3]);
                a[0] = a[1] = a[2] = a[3] = 0.f;
            }
        }

        if (kb < 2) { CP_WAIT0(); __syncthreads(); }
    }
}

// ===========================================================================
// kernel_launch
// ===========================================================================
extern "C" void kernel_launch(void* const* d_in, const int* in_sizes, int n_in,
                              void* d_out, int out_size)
{
    const float* A_in = (const float*)d_in[0];
    const float* B_in = (const float*)d_in[1];
    const float* C_in = (const float*)d_in[2];
    const float* A_W1 = (const float*)d_in[3];
    const float* A_b1 = (const float*)d_in[4];
    const float* A_W2 = (const float*)d_in[5];
    const float* A_b2 = (const float*)d_in[6];
    const float* B_W1 = (const float*)d_in[7];
    const float* B_b1 = (const float*)d_in[8];
    const float* B_W2 = (const float*)d_in[9];
    const float* B_b2 = (const float*)d_in[10];
    const float* C_W1 = (const float*)d_in[11];
    const float* C_b1 = (const float*)d_in[12];
    const float* C_W2 = (const float*)d_in[13];
    const float* C_b2 = (const float*)d_in[14];
    const float* C_W3 = (const float*)d_in[15];
    const float* C_b3 = (const float*)d_in[16];

    float* out = (float*)d_out;

    cudaFuncSetAttribute(contract_kernel,
                         cudaFuncAttributeMaxDynamicSharedMemorySize, SMEM_NEED);

    dim3 g1(NROW, 3);
    hidden_kernel<<<g1, MID>>>(A_in, B_in, C_in, A_W1, A_b1, B_W1, B_b1, C_W1, C_b1);

    dim3 g2(MID / 32, NROW / 32);                  // (8, 12)
    mid_gemm_kernel<<<g2, 256>>>(C_W2, C_b2);

    dim3 g3((NR + 31) / 32, NROW / 32, 3);         // (4, 12, 3)
    final_gemm_kernel<<<g3, 256>>>(A_W2, A_b2, B_W2, B_b2, C_W3, C_b3);

    dim3 grid(NROW / 128, NROW);                   // (3 j-tiles, 384 i)
    contract_kernel<<<grid, 512, SMEM_NEED>>>(out);
}

// round 8
// speedup vs baseline: 2.9525x; 1.0518x over previous
#include <cuda_runtime.h>
#include <cuda_bf16.h>
#include <math.h>
#include <stdint.h>

#define OMEGA 1.5f
#define NROW  384
#define MID   256
#define NR    100     // rank R
#define RP    112     // padded rank (K dim for MMA), 7 x k16

// Factor matrices, row-major padded K: g_X[row*RP + r], r<100 valid, rest 0
__device__ float g_A[NROW * RP];
__device__ float g_B[NROW * RP];
__device__ __nv_bfloat16 g_Chi[NROW * RP];   // C split hi
__device__ __nv_bfloat16 g_Clo[NROW * RP];   // C split lo

// MLP intermediates
__device__ float g_H[3 * NROW * MID];
__device__ float g_H2[NROW * MID];

// ===========================================================================
// helpers
// ===========================================================================
__device__ __forceinline__ uint32_t smem_u32(const void* p) {
    uint32_t a;
    asm("{ .reg .u64 t; cvta.to.shared.u64 t, %1; cvt.u32.u64 %0, t; }" : "=r"(a) : "l"(p));
    return a;
}
__device__ __forceinline__ void ldsm4(uint32_t addr, uint32_t r[4]) {
    asm volatile("ldmatrix.sync.aligned.m8n8.x4.shared.b16 {%0,%1,%2,%3}, [%4];"
                 : "=r"(r[0]), "=r"(r[1]), "=r"(r[2]), "=r"(r[3]) : "r"(addr));
}
__device__ __forceinline__ void mma16816(float d[4], const uint32_t* a,
                                         uint32_t b0, uint32_t b1) {
    asm volatile("mma.sync.aligned.m16n8k16.row.col.f32.bf16.bf16.f32 "
                 "{%0,%1,%2,%3}, {%4,%5,%6,%7}, {%8,%9}, {%0,%1,%2,%3};"
                 : "+f"(d[0]), "+f"(d[1]), "+f"(d[2]), "+f"(d[3])
                 : "r"(a[0]), "r"(a[1]), "r"(a[2]), "r"(a[3]), "r"(b0), "r"(b1));
}
__device__ __forceinline__ void split2(float x0, float x1, uint32_t& hi, uint32_t& lo) {
    __nv_bfloat16 h0 = __float2bfloat16(x0);
    __nv_bfloat16 h1 = __float2bfloat16(x1);
    __nv_bfloat16 l0 = __float2bfloat16(x0 - __bfloat162float(h0));
    __nv_bfloat16 l1 = __float2bfloat16(x1 - __bfloat162float(h1));
    hi = (uint32_t)__bfloat16_as_ushort(h0) | ((uint32_t)__bfloat16_as_ushort(h1) << 16);
    lo = (uint32_t)__bfloat16_as_ushort(l0) | ((uint32_t)__bfloat16_as_ushort(l1) << 16);
}
__device__ __forceinline__ void cp16(uint32_t dst, const void* src) {
    asm volatile("cp.async.cg.shared.global [%0], [%1], 16;" :: "r"(dst), "l"(src));
}
#define CP_COMMIT() asm volatile("cp.async.commit_group;" ::: "memory")
#define CP_WAIT0()  asm volatile("cp.async.wait_group 0;" ::: "memory")

// ===========================================================================
// Factor networks
// ===========================================================================
__global__ void hidden_kernel(const float* __restrict__ Ain,
                              const float* __restrict__ Bin,
                              const float* __restrict__ Cin,
                              const float* __restrict__ AW1, const float* __restrict__ Ab1,
                              const float* __restrict__ BW1, const float* __restrict__ Bb1,
                              const float* __restrict__ CW1, const float* __restrict__ Cb1)
{
    const int net = blockIdx.y;
    const int row = blockIdx.x;
    const int t   = threadIdx.x;
    const float x = (net == 0 ? Ain : net == 1 ? Bin : Cin)[row];
    const float* W1 = (net == 0 ? AW1 : net == 1 ? BW1 : CW1);
    const float* b1 = (net == 0 ? Ab1 : net == 1 ? Bb1 : Cb1);
    g_H[(net * NROW + row) * MID + t] = sinf(OMEGA * (x * W1[t] + b1[t]));
}

// 32x32 tile GEMM core, 256 threads, micro 2x2.
__device__ __forceinline__ void gemm32(const float* __restrict__ H,
                                       const float* __restrict__ W,
                                       int rb, int nb, int nout,
                                       float acc[2][2])
{
    __shared__ float sH[32][33];
    __shared__ float sW[32][33];
    const int tid = threadIdx.x;
    const int kk  = tid & 31;
    const int mm  = tid >> 5;        // 0..7
    const int tx  = tid & 15;
    const int ty  = tid >> 4;
    const int m0  = ty * 2;
    const int n0  = tx * 2;

    acc[0][0] = acc[0][1] = acc[1][0] = acc[1][1] = 0.f;

    for (int k0 = 0; k0 < MID; k0 += 32) {
        __syncthreads();
        #pragma unroll
        for (int s = 0; s < 4; s++) {
            const int r = mm + s * 8;
            sH[r][kk] = H[(rb + r) * MID + k0 + kk];
            const int n = nb + r;
            sW[r][kk] = (n < nout) ? W[n * MID + k0 + kk] : 0.f;
        }
        __syncthreads();
        #pragma unroll
        for (int k = 0; k < 32; k++) {
            const float h0 = sH[m0][k], h1 = sH[m0 + 1][k];
            const float w0 = sW[n0][k], w1 = sW[n0 + 1][k];
            acc[0][0] += h0 * w0; acc[0][1] += h0 * w1;
            acc[1][0] += h1 * w0; acc[1][1] += h1 * w1;
        }
    }
}

__global__ void __launch_bounds__(256) mid_gemm_kernel(const float* __restrict__ CW2,
                                                       const float* __restrict__ Cb2)
{
    const int rb = blockIdx.y * 32;
    const int nb = blockIdx.x * 32;
    float acc[2][2];
    gemm32(g_H + 2 * NROW * MID, CW2, rb, nb, MID, acc);
    const int tx = threadIdx.x & 15, ty = threadIdx.x >> 4;
    #pragma unroll
    for (int i = 0; i < 2; i++) {
        const int m = rb + ty * 2 + i;
        #pragma unroll
        for (int j = 0; j < 2; j++) {
            const int n = nb + tx * 2 + j;
            g_H2[m * MID + n] = sinf(OMEGA * (acc[i][j] + Cb2[n]));
        }
    }
}

__global__ void __launch_bounds__(256) final_gemm_kernel(const float* __restrict__ AW2,
                                                         const float* __restrict__ Ab2,
                                                         const float* __restrict__ BW2,
                                                         const float* __restrict__ Bb2,
                                                         const float* __restrict__ CW3,
                                                         const float* __restrict__ Cb3)
{
    const int net = blockIdx.z;
    const int rb  = blockIdx.y * 32;
    const int nb  = blockIdx.x * 32;
    const float* H = (net == 2) ? g_H2 : g_H + net * NROW * MID;
    const float* W = (net == 0) ? AW2 : (net == 1) ? BW2 : CW3;
    const float* b = (net == 0) ? Ab2 : (net == 1) ? Bb2 : Cb3;

    float acc[2][2];
    gemm32(H, W, rb, nb, NR, acc);
    const int tx = threadIdx.x & 15, ty = threadIdx.x >> 4;
    #pragma unroll
    for (int i = 0; i < 2; i++) {
        const int m = rb + ty * 2 + i;
        #pragma unroll
        for (int j = 0; j < 2; j++) {
            const int n = nb + tx * 2 + j;
            if (n < NR) {
                const float v = acc[i][j] + b[n];
                if (net == 0)      g_A[m * RP + n] = v;
                else if (net == 1) g_B[m * RP + n] = v;
                else {
                    __nv_bfloat16 h = __float2bfloat16(v);
                    g_Chi[m * RP + n] = h;
                    g_Clo[m * RP + n] = __float2bfloat16(v - __bfloat162float(h));
                }
            }
        }
    }
}

// ===========================================================================
// Contraction via HMMA bf16 3-pass split, FUSED passes.
// Block 512 = 16 warps (4m x 4n), warp tile 32(j) x 32(k).
// Per k-step: 8 ldsm4 (Mhi,Mlo,Chi,Clo) -> 24 MMAs (Mh*Ch + Ml*Ch + Mh*Cl).
// ===========================================================================
#define LDB 240
#define MT  (128 * LDB)              // 30720 bytes per [128 x 112] bf16 tile
#define OFF_MHI 0
#define OFF_MLO MT
#define OFF_C   (2 * MT)             // buf b at OFF_C + b*2*MT: {hi, lo}
#define SMEM_NEED (6 * MT)           // 184320 bytes

#define C_CHUNKS 1792                // 128 rows x 14 chunks of 16B per array

__device__ __forceinline__ void prefetch_C(uint32_t sb, int kt, int buf, int tid) {
    const uint32_t dst0 = sb + OFF_C + (uint32_t)(buf * 2 * MT);
    #pragma unroll
    for (int it = 0; it < 7; it++) {
        const int idx = tid + it * 512;          // 0..3583 = 2*1792
        const int arr = (idx >= C_CHUNKS) ? 1 : 0;   // 0=hi, 1=lo
        const int e   = idx - arr * C_CHUNKS;
        const int row = e / 14;
        const int ch  = e % 14;
        const __nv_bfloat16* src = (arr ? g_Clo : g_Chi) + (kt * 128 + row) * RP + ch * 8;
        cp16(dst0 + (uint32_t)(arr * MT + row * LDB + ch * 16), src);
    }
}

__global__ void __launch_bounds__(512, 1) contract_kernel(float* __restrict__ out)
{
    extern __shared__ __align__(16) char sm[];
    const uint32_t sbase = smem_u32(sm);

    const int tid  = threadIdx.x;
    const int lane = tid & 31;
    const int wid  = tid >> 5;
    const int i    = blockIdx.y;
    const int jb   = blockIdx.x * 128;

    const int wm = (wid & 3) * 32;    // m (j) offset
    const int wn = (wid >> 2) * 32;   // n (k) offset within kb tile

    // prefetch C tile 0, then convert M = A[i,:] * B[jb:,:] into hi/lo
    prefetch_C(sbase, 0, 0, tid);
    CP_COMMIT();

    #pragma unroll
    for (int it = 0; it < 14; it++) {
        const int idx = tid + it * 512;          // 0..7167 = 128 x 56
        const int j  = idx / 56;
        const int pr = idx % 56;
        const int r0 = pr * 2;
        float2 bv = make_float2(0.f, 0.f), av = make_float2(0.f, 0.f);
        if (pr < 50) {
            bv = *reinterpret_cast<const float2*>(&g_B[(jb + j) * RP + r0]);
            av = *reinterpret_cast<const float2*>(&g_A[i * RP + r0]);
        }
        uint32_t hi, lo;
        split2(av.x * bv.x, av.y * bv.y, hi, lo);
        const uint32_t off = (uint32_t)(j * LDB + pr * 4);
        *reinterpret_cast<uint32_t*>(sm + OFF_MHI + off) = hi;
        *reinterpret_cast<uint32_t*>(sm + OFF_MLO + off) = lo;
    }
    CP_WAIT0();
    __syncthreads();

    // fragment lane addresses
    const uint32_t aoff = (uint32_t)((lane & 15) * LDB + (lane >> 4) * 16);
    const uint32_t boff = (uint32_t)(((lane & 7) + ((lane >> 4) << 3)) * LDB
                                     + ((lane >> 3) & 1) * 16);
    const uint32_t mhiA = sbase + OFF_MHI + (uint32_t)(wm * LDB) + aoff;
    const uint32_t mloA = sbase + OFF_MLO + (uint32_t)(wm * LDB) + aoff;

    float acc[8][4];
    #pragma unroll
    for (int t = 0; t < 8; t++)
        #pragma unroll
        for (int q = 0; q < 4; q++) acc[t][q] = 0.f;

    const int g  = lane >> 2;
    const int c2 = (lane & 3) * 2;

    for (int kb = 0; kb < 3; kb++) {
        if (kb < 2) { prefetch_C(sbase, kb + 1, (kb + 1) & 1, tid); CP_COMMIT(); }

        const uint32_t cbuf = sbase + OFF_C + (uint32_t)((kb & 1) * 2 * MT);
        const uint32_t Bhi = cbuf + (uint32_t)(wn * LDB) + boff;
        const uint32_t Blo = Bhi + (uint32_t)MT;

        #pragma unroll
        for (int ks = 0; ks < 7; ks++) {
            uint32_t ah[8], al[8], bh[8], bl[8];
            ldsm4(mhiA + ks * 32, ah);
            ldsm4(mhiA + 16 * LDB + ks * 32, ah + 4);
            ldsm4(mloA + ks * 32, al);
            ldsm4(mloA + 16 * LDB + ks * 32, al + 4);
            ldsm4(Bhi + ks * 32, bh);
            ldsm4(Bhi + 16 * LDB + ks * 32, bh + 4);
            ldsm4(Blo + ks * 32, bl);
            ldsm4(Blo + 16 * LDB + ks * 32, bl + 4);
            #pragma unroll
            for (int nt = 0; nt < 4; nt++) {
                const uint32_t b0h = bh[nt * 2], b1h = bh[nt * 2 + 1];
                const uint32_t b0l = bl[nt * 2], b1l = bl[nt * 2 + 1];
                mma16816(acc[nt],     ah,     b0h, b1h);   // Mh*Ch
                mma16816(acc[4 + nt], ah + 4, b0h, b1h);
                mma16816(acc[nt],     al,     b0h, b1h);   // Ml*Ch
                mma16816(acc[4 + nt], al + 4, b0h, b1h);
                mma16816(acc[nt],     ah,     b0l, b1l);   // Mh*Cl
                mma16816(acc[4 + nt], ah + 4, b0l, b1l);
            }
        }

        // store this k-tile, reset acc
        #pragma unroll
        for (int mt = 0; mt < 2; mt++) {
            #pragma unroll
            for (int nt = 0; nt < 4; nt++) {
                float* p = out + ((size_t)i * NROW + (size_t)(jb + wm + mt * 16 + g)) * NROW
                               + (size_t)(kb * 128 + wn + nt * 8 + c2);
                float* a = acc[mt * 4 + nt];
                *reinterpret_cast<float2*>(p) = make_float2(a[0], a[1]);
                *reinterpret_cast<float2*>(p + (size_t)8 * NROW) = make_float2(a[2], a[3]);
                a[0] = a[1] = a[2] = a[3] = 0.f;
            }
        }

        if (kb < 2) { CP_WAIT0(); __syncthreads(); }
    }
}

// ===========================================================================
// kernel_launch
// ===========================================================================
extern "C" void kernel_launch(void* const* d_in, const int* in_sizes, int n_in,
                              void* d_out, int out_size)
{
    const float* A_in = (const float*)d_in[0];
    const float* B_in = (const float*)d_in[1];
    const float* C_in = (const float*)d_in[2];
    const float* A_W1 = (const float*)d_in[3];
    const float* A_b1 = (const float*)d_in[4];
    const float* A_W2 = (const float*)d_in[5];
    const float* A_b2 = (const float*)d_in[6];
    const float* B_W1 = (const float*)d_in[7];
    const float* B_b1 = (const float*)d_in[8];
    const float* B_W2 = (const float*)d_in[9];
    const float* B_b2 = (const float*)d_in[10];
    const float* C_W1 = (const float*)d_in[11];
    const float* C_b1 = (const float*)d_in[12];
    const float* C_W2 = (const float*)d_in[13];
    const float* C_b2 = (const float*)d_in[14];
    const float* C_W3 = (const float*)d_in[15];
    const float* C_b3 = (const float*)d_in[16];

    float* out = (float*)d_out;

    cudaFuncSetAttribute(contract_kernel,
                         cudaFuncAttributeMaxDynamicSharedMemorySize, SMEM_NEED);

    dim3 g1(NROW, 3);
    hidden_kernel<<<g1, MID>>>(A_in, B_in, C_in, A_W1, A_b1, B_W1, B_b1, C_W1, C_b1);

    dim3 g2(MID / 32, NROW / 32);                  // (8, 12)
    mid_gemm_kernel<<<g2, 256>>>(C_W2, C_b2);

    dim3 g3((NR + 31) / 32, NROW / 32, 3);         // (4, 12, 3)
    final_gemm_kernel<<<g3, 256>>>(A_W2, A_b2, B_W2, B_b2, C_W3, C_b3);

    dim3 grid(NROW / 128, NROW);                   // (3 j-tiles, 384 i)
    contract_kernel<<<grid, 512, SMEM_NEED>>>(out);
}

// round 9
// speedup vs baseline: 4.2693x; 1.4460x over previous
#include <cuda_runtime.h>
#include <cuda_fp16.h>
#include <cuda_bf16.h>
#include <math.h>
#include <stdint.h>

#define OMEGA 1.5f
#define NROW  384
#define MID   256
#define NR    100     // rank R
#define RP    112     // padded rank (K dim for MMA), 7 x k16

// Factor matrices, row-major padded K: g_X[row*RP + r], r<100 valid, rest 0
__device__ float g_A[NROW * RP];
__device__ float g_B[NROW * RP];
__device__ __half g_Ch[NROW * RP];     // C rounded to fp16

// MLP intermediates
__device__ float g_H[3 * NROW * MID];
__device__ float g_H2[NROW * MID];

// ===========================================================================
// helpers
// ===========================================================================
__device__ __forceinline__ uint32_t smem_u32(const void* p) {
    uint32_t a;
    asm("{ .reg .u64 t; cvta.to.shared.u64 t, %1; cvt.u32.u64 %0, t; }" : "=r"(a) : "l"(p));
    return a;
}
__device__ __forceinline__ void ldsm4(uint32_t addr, uint32_t r[4]) {
    asm volatile("ldmatrix.sync.aligned.m8n8.x4.shared.b16 {%0,%1,%2,%3}, [%4];"
                 : "=r"(r[0]), "=r"(r[1]), "=r"(r[2]), "=r"(r[3]) : "r"(addr));
}
__device__ __forceinline__ void mma16816(float d[4], const uint32_t* a,
                                         uint32_t b0, uint32_t b1) {
    asm volatile("mma.sync.aligned.m16n8k16.row.col.f32.f16.f16.f32 "
                 "{%0,%1,%2,%3}, {%4,%5,%6,%7}, {%8,%9}, {%0,%1,%2,%3};"
                 : "+f"(d[0]), "+f"(d[1]), "+f"(d[2]), "+f"(d[3])
                 : "r"(a[0]), "r"(a[1]), "r"(a[2]), "r"(a[3]), "r"(b0), "r"(b1));
}
// fp16 hi/lo split of two floats, packed
__device__ __forceinline__ void split2h(float x0, float x1, uint32_t& hi, uint32_t& lo) {
    __half h0 = __float2half_rn(x0);
    __half h1 = __float2half_rn(x1);
    __half l0 = __float2half_rn(x0 - __half2float(h0));
    __half l1 = __float2half_rn(x1 - __half2float(h1));
    hi = (uint32_t)__half_as_ushort(h0) | ((uint32_t)__half_as_ushort(h1) << 16);
    lo = (uint32_t)__half_as_ushort(l0) | ((uint32_t)__half_as_ushort(l1) << 16);
}
__device__ __forceinline__ void cp16(uint32_t dst, const void* src) {
    asm volatile("cp.async.cg.shared.global [%0], [%1], 16;" :: "r"(dst), "l"(src));
}
#define CP_COMMIT() asm volatile("cp.async.commit_group;" ::: "memory")
#define CP_WAIT0()  asm volatile("cp.async.wait_group 0;" ::: "memory")

// ===========================================================================
// Factor networks
// ===========================================================================
__global__ void hidden_kernel(const float* __restrict__ Ain,
                              const float* __restrict__ Bin,
                              const float* __restrict__ Cin,
                              const float* __restrict__ AW1, const float* __restrict__ Ab1,
                              const float* __restrict__ BW1, const float* __restrict__ Bb1,
                              const float* __restrict__ CW1, const float* __restrict__ Cb1)
{
    const int net = blockIdx.y;
    const int row = blockIdx.x;
    const int t   = threadIdx.x;
    const float x = (net == 0 ? Ain : net == 1 ? Bin : Cin)[row];
    const float* W1 = (net == 0 ? AW1 : net == 1 ? BW1 : CW1);
    const float* b1 = (net == 0 ? Ab1 : net == 1 ? Bb1 : Cb1);
    g_H[(net * NROW + row) * MID + t] = sinf(OMEGA * (x * W1[t] + b1[t]));
}

// 32x32 tile GEMM core, 256 threads, micro 2x2.
__device__ __forceinline__ void gemm32(const float* __restrict__ H,
                                       const float* __restrict__ W,
                                       int rb, int nb, int nout,
                                       float acc[2][2])
{
    __shared__ float sH[32][33];
    __shared__ float sW[32][33];
    const int tid = threadIdx.x;
    const int kk  = tid & 31;
    const int mm  = tid >> 5;        // 0..7
    const int tx  = tid & 15;
    const int ty  = tid >> 4;
    const int m0  = ty * 2;
    const int n0  = tx * 2;

    acc[0][0] = acc[0][1] = acc[1][0] = acc[1][1] = 0.f;

    for (int k0 = 0; k0 < MID; k0 += 32) {
        __syncthreads();
        #pragma unroll
        for (int s = 0; s < 4; s++) {
            const int r = mm + s * 8;
            sH[r][kk] = H[(rb + r) * MID + k0 + kk];
            const int n = nb + r;
            sW[r][kk] = (n < nout) ? W[n * MID + k0 + kk] : 0.f;
        }
        __syncthreads();
        #pragma unroll
        for (int k = 0; k < 32; k++) {
            const float h0 = sH[m0][k], h1 = sH[m0 + 1][k];
            const float w0 = sW[n0][k], w1 = sW[n0 + 1][k];
            acc[0][0] += h0 * w0; acc[0][1] += h0 * w1;
            acc[1][0] += h1 * w0; acc[1][1] += h1 * w1;
        }
    }
}

__global__ void __launch_bounds__(256) mid_gemm_kernel(const float* __restrict__ CW2,
                                                       const float* __restrict__ Cb2)
{
    const int rb = blockIdx.y * 32;
    const int nb = blockIdx.x * 32;
    float acc[2][2];
    gemm32(g_H + 2 * NROW * MID, CW2, rb, nb, MID, acc);
    const int tx = threadIdx.x & 15, ty = threadIdx.x >> 4;
    #pragma unroll
    for (int i = 0; i < 2; i++) {
        const int m = rb + ty * 2 + i;
        #pragma unroll
        for (int j = 0; j < 2; j++) {
            const int n = nb + tx * 2 + j;
            g_H2[m * MID + n] = sinf(OMEGA * (acc[i][j] + Cb2[n]));
        }
    }
}

__global__ void __launch_bounds__(256) final_gemm_kernel(const float* __restrict__ AW2,
                                                         const float* __restrict__ Ab2,
                                                         const float* __restrict__ BW2,
                                                         const float* __restrict__ Bb2,
                                                         const float* __restrict__ CW3,
                                                         const float* __restrict__ Cb3)
{
    const int net = blockIdx.z;
    const int rb  = blockIdx.y * 32;
    const int nb  = blockIdx.x * 32;
    const float* H = (net == 2) ? g_H2 : g_H + net * NROW * MID;
    const float* W = (net == 0) ? AW2 : (net == 1) ? BW2 : CW3;
    const float* b = (net == 0) ? Ab2 : (net == 1) ? Bb2 : Cb3;

    float acc[2][2];
    gemm32(H, W, rb, nb, NR, acc);
    const int tx = threadIdx.x & 15, ty = threadIdx.x >> 4;
    #pragma unroll
    for (int i = 0; i < 2; i++) {
        const int m = rb + ty * 2 + i;
        #pragma unroll
        for (int j = 0; j < 2; j++) {
            const int n = nb + tx * 2 + j;
            if (n < NR) {
                const float v = acc[i][j] + b[n];
                if (net == 0)      g_A[m * RP + n] = v;
                else if (net == 1) g_B[m * RP + n] = v;
                else               g_Ch[m * RP + n] = __float2half_rn(v);
            }
        }
    }
}

// ===========================================================================
// Contraction: HMMA fp16 2-pass (M split hi/lo fp16; C rounded to fp16).
// Block 256 = 8 warps (4m x 2n), warp tile 32(j) x 64(k).
// CTA = (jb, i): 128j x 384k as 3 kb iterations of 128k.
// Per k-step per warp: 8 ldsm4 (ah,al,bh) -> 32 MMAs (Mh*Ch + Ml*Ch).
// smem ~92KB -> 2 CTAs/SM (regs capped at 128 via launch_bounds(256,2)).
// ===========================================================================
#define LDB 240
#define MT  (128 * LDB)              // 30720 bytes per [128 x 112] fp16 tile
#define OFF_MHI 0
#define OFF_MLO MT
#define OFF_C   (2 * MT)             // single C buffer
#define SMEM_NEED (3 * MT)           // 92160 bytes

__device__ __forceinline__ void prefetch_C(uint32_t sb, int kt, int tid) {
    const uint32_t dst0 = sb + OFF_C;
    #pragma unroll
    for (int it = 0; it < 7; it++) {
        const int idx = tid + it * 256;          // 0..1791 = 128 rows x 14 chunks
        const int row = idx / 14;
        const int ch  = idx % 14;
        const __half* src = g_Ch + (kt * 128 + row) * RP + ch * 8;
        cp16(dst0 + (uint32_t)(row * LDB + ch * 16), src);
    }
}

__global__ void __launch_bounds__(256, 2) contract_kernel(float* __restrict__ out)
{
    extern __shared__ __align__(16) char sm[];
    const uint32_t sbase = smem_u32(sm);

    const int tid  = threadIdx.x;
    const int lane = tid & 31;
    const int wid  = tid >> 5;
    const int i    = blockIdx.y;
    const int jb   = blockIdx.x * 128;

    const int wm = (wid & 3) * 32;    // m (j) offset
    const int wn = (wid >> 2) * 64;   // n (k) offset within kb tile

    // prefetch C tile 0, then convert M = A[i,:] * B[jb:,:] into fp16 hi/lo
    prefetch_C(sbase, 0, tid);
    CP_COMMIT();

    #pragma unroll
    for (int it = 0; it < 28; it++) {
        const int idx = tid + it * 256;          // 0..7167 = 128 x 56
        const int j  = idx / 56;
        const int pr = idx % 56;
        const int r0 = pr * 2;
        float2 bv = make_float2(0.f, 0.f), av = make_float2(0.f, 0.f);
        if (pr < 50) {
            bv = *reinterpret_cast<const float2*>(&g_B[(jb + j) * RP + r0]);
            av = *reinterpret_cast<const float2*>(&g_A[i * RP + r0]);
        }
        uint32_t hi, lo;
        split2h(av.x * bv.x, av.y * bv.y, hi, lo);
        const uint32_t off = (uint32_t)(j * LDB + pr * 4);
        *reinterpret_cast<uint32_t*>(sm + OFF_MHI + off) = hi;
        *reinterpret_cast<uint32_t*>(sm + OFF_MLO + off) = lo;
    }
    CP_WAIT0();
    __syncthreads();

    // fragment lane addresses
    const uint32_t aoff = (uint32_t)((lane & 15) * LDB + (lane >> 4) * 16);
    const uint32_t boff = (uint32_t)(((lane & 7) + ((lane >> 4) << 3)) * LDB
                                     + ((lane >> 3) & 1) * 16);
    const uint32_t mhiA = sbase + OFF_MHI + (uint32_t)(wm * LDB) + aoff;
    const uint32_t mloA = sbase + OFF_MLO + (uint32_t)(wm * LDB) + aoff;
    const uint32_t Bb   = sbase + OFF_C + (uint32_t)(wn * LDB) + boff;

    float acc[16][4];
    #pragma unroll
    for (int t = 0; t < 16; t++)
        #pragma unroll
        for (int q = 0; q < 4; q++) acc[t][q] = 0.f;

    const int g  = lane >> 2;
    const int c2 = (lane & 3) * 2;

    for (int kb = 0; kb < 3; kb++) {
        #pragma unroll
        for (int ks = 0; ks < 7; ks++) {
            uint32_t ah[8], al[8], bh[16];
            ldsm4(mhiA + ks * 32, ah);
            ldsm4(mhiA + 16 * LDB + ks * 32, ah + 4);
            ldsm4(mloA + ks * 32, al);
            ldsm4(mloA + 16 * LDB + ks * 32, al + 4);
            #pragma unroll
            for (int p = 0; p < 4; p++)
                ldsm4(Bb + (uint32_t)(p * 16 * LDB) + ks * 32, bh + 4 * p);
            #pragma unroll
            for (int nt = 0; nt < 8; nt++) {
                const uint32_t b0 = bh[nt * 2], b1 = bh[nt * 2 + 1];
                mma16816(acc[nt],     ah,     b0, b1);   // Mh*Ch
                mma16816(acc[8 + nt], ah + 4, b0, b1);
                mma16816(acc[nt],     al,     b0, b1);   // Ml*Ch
                mma16816(acc[8 + nt], al + 4, b0, b1);
            }
        }

        // store this k-tile, reset acc
        #pragma unroll
        for (int mt = 0; mt < 2; mt++) {
            #pragma unroll
            for (int nt = 0; nt < 8; nt++) {
                float* p = out + ((size_t)i * NROW + (size_t)(jb + wm + mt * 16 + g)) * NROW
                               + (size_t)(kb * 128 + wn + nt * 8 + c2);
                float* a = acc[mt * 8 + nt];
                *reinterpret_cast<float2*>(p) = make_float2(a[0], a[1]);
                *reinterpret_cast<float2*>(p + (size_t)8 * NROW) = make_float2(a[2], a[3]);
                a[0] = a[1] = a[2] = a[3] = 0.f;
            }
        }

        if (kb < 2) {
            __syncthreads();                     // all warps done reading C buffer
            prefetch_C(sbase, kb + 1, tid);
            CP_COMMIT();
            CP_WAIT0();
            __syncthreads();
        }
    }
}

// ===========================================================================
// kernel_launch
// ===========================================================================
extern "C" void kernel_launch(void* const* d_in, const int* in_sizes, int n_in,
                              void* d_out, int out_size)
{
    const float* A_in = (const float*)d_in[0];
    const float* B_in = (const float*)d_in[1];
    const float* C_in = (const float*)d_in[2];
    const float* A_W1 = (const float*)d_in[3];
    const float* A_b1 = (const float*)d_in[4];
    const float* A_W2 = (const float*)d_in[5];
    const float* A_b2 = (const float*)d_in[6];
    const float* B_W1 = (const float*)d_in[7];
    const float* B_b1 = (const float*)d_in[8];
    const float* B_W2 = (const float*)d_in[9];
    const float* B_b2 = (const float*)d_in[10];
    const float* C_W1 = (const float*)d_in[11];
    const float* C_b1 = (const float*)d_in[12];
    const float* C_W2 = (const float*)d_in[13];
    const float* C_b2 = (const float*)d_in[14];
    const float* C_W3 = (const float*)d_in[15];
    const float* C_b3 = (const float*)d_in[16];

    float* out = (float*)d_out;

    cudaFuncSetAttribute(contract_kernel,
                         cudaFuncAttributeMaxDynamicSharedMemorySize, SMEM_NEED);

    dim3 g1(NROW, 3);
    hidden_kernel<<<g1, MID>>>(A_in, B_in, C_in, A_W1, A_b1, B_W1, B_b1, C_W1, C_b1);

    dim3 g2(MID / 32, NROW / 32);                  // (8, 12)
    mid_gemm_kernel<<<g2, 256>>>(C_W2, C_b2);

    dim3 g3((NR + 31) / 32, NROW / 32, 3);         // (4, 12, 3)
    final_gemm_kernel<<<g3, 256>>>(A_W2, A_b2, B_W2, B_b2, C_W3, C_b3);

    dim3 grid(NROW / 128, NROW);                   // (3 j-tiles, 384 i)
    contract_kernel<<<grid, 256, SMEM_NEED>>>(out);
}